// round 1
// baseline (speedup 1.0000x reference)
#include <cuda_runtime.h>

// Problem constants (fixed shapes from reference)
#define VV 100000
#define DD 64
#define BB 4096
#define LL 50
#define KK 3
#define NBAGS (BB * (2 + KK))   // 20480
#define MAX_NORM 20.0f

// Renormed embedding table (25.6 MB) — __device__ global scratch (no allocs allowed).
__device__ float d_table[VV * DD];

// Kernel 1: renorm rows with norm > MAX_NORM, write scaled table.
// One half-warp (16 lanes) per row; each lane holds a float4 (16*4 = 64 floats).
__global__ __launch_bounds__(256) void renorm_kernel(const float* __restrict__ emb) {
    int idx  = blockIdx.x * blockDim.x + threadIdx.x;
    int row  = idx >> 4;
    int lane = threadIdx.x & 15;
    if (row >= VV) return;

    const float4* e4 = (const float4*)emb;
    float4 v = e4[row * 16 + lane];

    float ss = v.x * v.x + v.y * v.y + v.z * v.z + v.w * v.w;
    // xor masks 1,2,4,8 stay within the 16-lane half-warp
    ss += __shfl_xor_sync(0xffffffffu, ss, 1);
    ss += __shfl_xor_sync(0xffffffffu, ss, 2);
    ss += __shfl_xor_sync(0xffffffffu, ss, 4);
    ss += __shfl_xor_sync(0xffffffffu, ss, 8);

    float norm = sqrtf(ss);
    float s = (norm > MAX_NORM) ? (MAX_NORM / norm) : 1.0f;

    float4 o;
    o.x = v.x * s; o.y = v.y * s; o.z = v.z * s; o.w = v.w * s;
    ((float4*)d_table)[row * 16 + lane] = o;
}

// Kernel 2: embedding-bag sum. One half-warp per bag, float4 per lane.
// Bag order matches output tuple flatten: [l (B bags) | r (B bags) | neg (B*K bags)].
__global__ __launch_bounds__(256) void bag_kernel(
    const int* __restrict__ tl,
    const int* __restrict__ tr,
    const int* __restrict__ tn,
    float* __restrict__ out)
{
    int idx  = blockIdx.x * blockDim.x + threadIdx.x;
    int bag  = idx >> 4;
    int lane = threadIdx.x & 15;
    if (bag >= NBAGS) return;

    const int* p;
    if (bag < BB)          p = tl + bag * LL;
    else if (bag < 2 * BB) p = tr + (bag - BB) * LL;
    else                   p = tn + (bag - 2 * BB) * LL;

    const float4* t4 = (const float4*)d_table;
    float4 acc = make_float4(0.f, 0.f, 0.f, 0.f);

    // unroll 10: batches 10 independent token loads + 10 gathers per group → MLP
    #pragma unroll 10
    for (int t = 0; t < LL; ++t) {
        int tok = p[t];                       // broadcast across half-warp
        float4 v = __ldg(&t4[tok * 16 + lane]);
        acc.x += v.x; acc.y += v.y; acc.z += v.z; acc.w += v.w;
    }

    ((float4*)out)[bag * 16 + lane] = acc;
}

extern "C" void kernel_launch(void* const* d_in, const int* in_sizes, int n_in,
                              void* d_out, int out_size) {
    const float* emb = (const float*)d_in[0];
    const int*   tl  = (const int*)d_in[1];
    const int*   tr  = (const int*)d_in[2];
    const int*   tn  = (const int*)d_in[3];
    float*       out = (float*)d_out;

    // 16 half-warps (rows) per 256-thread block
    int renorm_blocks = (VV + 15) / 16;          // 6250
    renorm_kernel<<<renorm_blocks, 256>>>(emb);

    int bag_blocks = NBAGS / 16;                 // 1280
    bag_kernel<<<bag_blocks, 256>>>(tl, tr, tn, out);
}

// round 2
// speedup vs baseline: 1.4024x; 1.4024x over previous
#include <cuda_runtime.h>
#include <cuda_fp16.h>

// Problem constants (fixed shapes from reference)
#define VV 100000
#define DD 64
#define BB 4096
#define LL 50
#define KK 3
#define NBAGS (BB * (2 + KK))   // 20480
#define MAX_NORM 20.0f

// Renormed embedding table in fp16 (12.8 MB) — halves L2 gather traffic vs f32.
__device__ __half d_table[VV * DD];

// Kernel 1: renorm rows with norm > MAX_NORM, write scaled fp16 table.
// One half-warp (16 lanes) per row; each lane holds a float4 (16*4 = 64 floats),
// writes 4 halves (8 B).
__global__ __launch_bounds__(256) void renorm_kernel(const float* __restrict__ emb) {
    int idx  = blockIdx.x * blockDim.x + threadIdx.x;
    int row  = idx >> 4;
    int lane = threadIdx.x & 15;
    if (row >= VV) return;

    const float4* e4 = (const float4*)emb;
    float4 v = e4[row * 16 + lane];

    float ss = v.x * v.x + v.y * v.y + v.z * v.z + v.w * v.w;
    ss += __shfl_xor_sync(0xffffffffu, ss, 1);
    ss += __shfl_xor_sync(0xffffffffu, ss, 2);
    ss += __shfl_xor_sync(0xffffffffu, ss, 4);
    ss += __shfl_xor_sync(0xffffffffu, ss, 8);

    float norm = sqrtf(ss);
    float s = (norm > MAX_NORM) ? (MAX_NORM / norm) : 1.0f;

    __half2 h0 = __floats2half2_rn(v.x * s, v.y * s);
    __half2 h1 = __floats2half2_rn(v.z * s, v.w * s);
    uint2 packed;
    packed.x = *reinterpret_cast<unsigned*>(&h0);
    packed.y = *reinterpret_cast<unsigned*>(&h1);
    ((uint2*)d_table)[row * 16 + lane] = packed;
}

// Kernel 2: embedding-bag sum over fp16 table, f32 accumulation.
// 8 lanes per bag; each lane loads uint4 = 8 halves (16 B) per token.
// One token-gather = 8 lanes * 16 B = 128 B = one L2 line.
// Bag order matches output tuple flatten: [l (B) | r (B) | neg (B*K)].
__global__ __launch_bounds__(256) void bag_kernel(
    const int* __restrict__ tl,
    const int* __restrict__ tr,
    const int* __restrict__ tn,
    float* __restrict__ out)
{
    int idx  = blockIdx.x * blockDim.x + threadIdx.x;
    int bag  = idx >> 3;
    int lane = threadIdx.x & 7;
    if (bag >= NBAGS) return;

    const int* p;
    if (bag < BB)          p = tl + bag * LL;
    else if (bag < 2 * BB) p = tr + (bag - BB) * LL;
    else                   p = tn + (bag - 2 * BB) * LL;

    const uint4* t4 = (const uint4*)d_table;   // 8 halves per uint4, 8 uint4 per row
    float acc[8] = {0.f, 0.f, 0.f, 0.f, 0.f, 0.f, 0.f, 0.f};

    // unroll 10: batches independent token loads + gathers for MLP
    #pragma unroll 10
    for (int t = 0; t < LL; ++t) {
        int tok = p[t];                         // broadcast across the 8-lane group
        uint4 v = __ldg(&t4[tok * 8 + lane]);
        __half2 a = *reinterpret_cast<__half2*>(&v.x);
        __half2 b = *reinterpret_cast<__half2*>(&v.y);
        __half2 c = *reinterpret_cast<__half2*>(&v.z);
        __half2 d = *reinterpret_cast<__half2*>(&v.w);
        float2 fa = __half22float2(a);
        float2 fb = __half22float2(b);
        float2 fc = __half22float2(c);
        float2 fd = __half22float2(d);
        acc[0] += fa.x; acc[1] += fa.y;
        acc[2] += fb.x; acc[3] += fb.y;
        acc[4] += fc.x; acc[5] += fc.y;
        acc[6] += fd.x; acc[7] += fd.y;
    }

    // Each lane owns 8 consecutive dims: write two float4s.
    float4* o4 = (float4*)out;
    o4[bag * 16 + lane * 2 + 0] = make_float4(acc[0], acc[1], acc[2], acc[3]);
    o4[bag * 16 + lane * 2 + 1] = make_float4(acc[4], acc[5], acc[6], acc[7]);
}

extern "C" void kernel_launch(void* const* d_in, const int* in_sizes, int n_in,
                              void* d_out, int out_size) {
    const float* emb = (const float*)d_in[0];
    const int*   tl  = (const int*)d_in[1];
    const int*   tr  = (const int*)d_in[2];
    const int*   tn  = (const int*)d_in[3];
    float*       out = (float*)d_out;

    int renorm_blocks = (VV + 15) / 16;          // 6250 (16 rows per 256-thread block)
    renorm_kernel<<<renorm_blocks, 256>>>(emb);

    int bag_blocks = NBAGS / 32;                 // 640 (32 bags per 256-thread block)
    bag_kernel<<<bag_blocks, 256>>>(tl, tr, tn, out);
}

// round 3
// speedup vs baseline: 1.5333x; 1.0933x over previous
#include <cuda_runtime.h>
#include <cuda_fp16.h>

// Problem constants (fixed shapes from reference)
#define VV 100000
#define DD 64
#define BB 4096
#define LL 50
#define KK 3
#define NBAGS (BB * (2 + KK))   // 20480
#define MAX_NORM 20.0f

// Renormed embedding table in fp16 (12.8 MB).
__device__ __half d_table[VV * DD];

// Kernel 1: renorm rows. 8 lanes per row; each lane reads 8 floats (2x float4),
// reduces norm across 8 lanes, writes 8 halves (uint4, 16 B).
__global__ __launch_bounds__(256) void renorm_kernel(const float* __restrict__ emb) {
    int idx  = blockIdx.x * blockDim.x + threadIdx.x;
    int row  = idx >> 3;
    int lane = threadIdx.x & 7;
    if (row >= VV) return;

    const float4* e4 = (const float4*)emb;
    float4 v0 = e4[row * 16 + lane * 2 + 0];
    float4 v1 = e4[row * 16 + lane * 2 + 1];

    float ss = v0.x*v0.x + v0.y*v0.y + v0.z*v0.z + v0.w*v0.w
             + v1.x*v1.x + v1.y*v1.y + v1.z*v1.z + v1.w*v1.w;
    ss += __shfl_xor_sync(0xffffffffu, ss, 1);
    ss += __shfl_xor_sync(0xffffffffu, ss, 2);
    ss += __shfl_xor_sync(0xffffffffu, ss, 4);

    float norm = sqrtf(ss);
    float s = (norm > MAX_NORM) ? (MAX_NORM / norm) : 1.0f;

    __half2 h0 = __floats2half2_rn(v0.x * s, v0.y * s);
    __half2 h1 = __floats2half2_rn(v0.z * s, v0.w * s);
    __half2 h2 = __floats2half2_rn(v1.x * s, v1.y * s);
    __half2 h3 = __floats2half2_rn(v1.z * s, v1.w * s);
    uint4 packed;
    packed.x = *reinterpret_cast<unsigned*>(&h0);
    packed.y = *reinterpret_cast<unsigned*>(&h1);
    packed.z = *reinterpret_cast<unsigned*>(&h2);
    packed.w = *reinterpret_cast<unsigned*>(&h3);
    ((uint4*)d_table)[row * 8 + lane] = packed;
}

// Kernel 2: embedding-bag sum over fp16 table, f32 accumulation.
// 16 lanes per bag = two 8-lane sub-groups; sub-group g sums tokens
// [g*25, g*25+25). Each lane loads uint4 = 8 halves (16 B) per token, so one
// token-gather per sub-group = 128 B = one L2 line. Partials are combined with
// shfl_xor(8) (the 16 lanes of a bag are warp-contiguous).
// Bag order matches output tuple flatten: [l (B) | r (B) | neg (B*K)].
__global__ __launch_bounds__(256) void bag_kernel(
    const int* __restrict__ tl,
    const int* __restrict__ tr,
    const int* __restrict__ tn,
    float* __restrict__ out)
{
    int idx   = blockIdx.x * blockDim.x + threadIdx.x;
    int bag   = idx >> 4;
    int sub   = (threadIdx.x >> 3) & 1;   // which 25-token half
    int lane  = threadIdx.x & 7;          // which 16 B of the row
    if (bag >= NBAGS) return;

    const int* p;
    if (bag < BB)          p = tl + bag * LL;
    else if (bag < 2 * BB) p = tr + (bag - BB) * LL;
    else                   p = tn + (bag - 2 * BB) * LL;
    p += sub * 25;

    const uint4* t4 = (const uint4*)d_table;   // 8 uint4 per row
    float acc[8] = {0.f, 0.f, 0.f, 0.f, 0.f, 0.f, 0.f, 0.f};

    #pragma unroll 5
    for (int t = 0; t < 25; ++t) {
        int tok = p[t];                        // uniform across the 8-lane group
        uint4 v = __ldg(&t4[tok * 8 + lane]);
        __half2 a = *reinterpret_cast<__half2*>(&v.x);
        __half2 b = *reinterpret_cast<__half2*>(&v.y);
        __half2 c = *reinterpret_cast<__half2*>(&v.z);
        __half2 d = *reinterpret_cast<__half2*>(&v.w);
        float2 fa = __half22float2(a);
        float2 fb = __half22float2(b);
        float2 fc = __half22float2(c);
        float2 fd = __half22float2(d);
        acc[0] += fa.x; acc[1] += fa.y;
        acc[2] += fb.x; acc[3] += fb.y;
        acc[4] += fc.x; acc[5] += fc.y;
        acc[6] += fd.x; acc[7] += fd.y;
    }

    // Combine the two 25-token partials (lanes i and i^8 hold same dims).
    #pragma unroll
    for (int i = 0; i < 8; ++i)
        acc[i] += __shfl_xor_sync(0xffffffffu, acc[i], 8);

    // 16 threads of the bag write 16 float4s (64 floats).
    // Thread (sub, lane) writes float4 slot lane*2 + sub from acc[sub*4 ..].
    float4* o4 = (float4*)out;
    float4 w = make_float4(acc[sub * 4 + 0], acc[sub * 4 + 1],
                           acc[sub * 4 + 2], acc[sub * 4 + 3]);
    o4[bag * 16 + lane * 2 + sub] = w;
}

extern "C" void kernel_launch(void* const* d_in, const int* in_sizes, int n_in,
                              void* d_out, int out_size) {
    const float* emb = (const float*)d_in[0];
    const int*   tl  = (const int*)d_in[1];
    const int*   tr  = (const int*)d_in[2];
    const int*   tn  = (const int*)d_in[3];
    float*       out = (float*)d_out;

    int renorm_blocks = (VV * 8 + 255) / 256;    // 3125 (32 rows per block)
    renorm_kernel<<<renorm_blocks, 256>>>(emb);

    int bag_blocks = NBAGS * 16 / 256;           // 1280 (16 bags per block)
    bag_kernel<<<bag_blocks, 256>>>(tl, tr, tn, out);
}